// round 15
// baseline (speedup 1.0000x reference)
#include <cuda_runtime.h>

#define DD  128
#define N1C 50000
#define N2C 5000
#define E1C 1000000
#define E2C 50000

#define S1B 49          // ceil(N1C/1024)
#define S2B 5           // ceil(N2C/1024)
#define SB  (S1B + S2B)

// Scratch (device globals — no allocation allowed; zero-initialized at load)
__device__ float g_agg1[N1C * DD];   // tf32-rounded mean after k_agg<1>
__device__ float g_h[N1C * DD];
__device__ float g_agg2[N2C * DD];   // fp32 mean (layer-2 is fp32 SIMT)
__device__ float g_W1l[DD * DD], g_W1r[DD * DD];   // tf32-rounded weights
__device__ int g_cnt1[N1C], g_off1[N1C + 1], g_cur1[N1C];
__device__ int g_cnt2[N2C], g_off2[N2C + 1], g_cur2[N2C];
__device__ int g_srt1[E1C], g_srt2[E2C];
__device__ int g_bsum[SB];

__device__ __forceinline__ float f2tf_rna(float f) {
    unsigned u;
    asm("cvt.rna.tf32.f32 %0, %1;" : "=r"(u) : "f"(f));
    return __uint_as_float(u);
}

// ---- degree histogram (8 edges/thread) + tf32 weight rounding fold-in;
//      cnt zero on entry — invariant re-established by k_s3 ----
__global__ void k_hist(const int* __restrict__ dst1,
                       const int* __restrict__ dst2, int E1, int E2,
                       const float* __restrict__ Wl,
                       const float* __restrict__ Wr) {
    int t  = blockIdx.x * blockDim.x + threadIdx.x;
    if (t < DD * DD) {
        g_W1l[t] = f2tf_rna(Wl[t]);
        g_W1r[t] = f2tf_rna(Wr[t]);
    }
    int T1 = (E1 + 7) >> 3;
    if (t < T1) {
        int base = t * 8;
#pragma unroll
        for (int k = 0; k < 8; ++k) {
            int i = base + k;
            if (i < E1) atomicAdd(&g_cnt1[dst1[i]], 1);
        }
    } else {
        int base = (t - T1) * 8;
        if (base < E2) {
#pragma unroll
            for (int k = 0; k < 8; ++k) {
                int i = base + k;
                if (i < E2) atomicAdd(&g_cnt2[dst2[i]], 1);
            }
        }
    }
}

// ---- scan phase 1: per-block (1024 elems) totals ----
__global__ void k_s1() {
    __shared__ int ws[8];
    int b = blockIdx.x, tid = threadIdx.x;
    const int* cnt; int n, base;
    if (b < S1B) { cnt = g_cnt1; n = N1C; base = b * 1024; }
    else         { cnt = g_cnt2; n = N2C; base = (b - S1B) * 1024; }

    int s = 0, i0 = base + tid * 4;
#pragma unroll
    for (int k = 0; k < 4; ++k) {
        int idx = i0 + k;
        if (idx < n) s += cnt[idx];
    }
    for (int o = 16; o; o >>= 1) s += __shfl_down_sync(~0u, s, o);
    if ((tid & 31) == 0) ws[tid >> 5] = s;
    __syncthreads();
    if (tid == 0) {
        int tot = 0;
#pragma unroll
        for (int w = 0; w < 8; ++w) tot += ws[w];
        g_bsum[b] = tot;
    }
}

// ---- scan phase 2+3 fused; zeroes cnt after use (restores invariant) ----
__global__ void k_s3() {
    __shared__ int wsum[8];
    __shared__ int sb[SB];
    __shared__ int s_boff;
    int b = blockIdx.x, tid = threadIdx.x;
    int lane = tid & 31, wid = tid >> 5;
    int* cnt; int* off; int* cur; int n, base;
    if (b < S1B) { cnt = g_cnt1; off = g_off1; cur = g_cur1; n = N1C; base = b * 1024; }
    else { cnt = g_cnt2; off = g_off2; cur = g_cur2; n = N2C; base = (b - S1B) * 1024; }

    if (tid < SB) sb[tid] = g_bsum[tid];
    __syncthreads();
    if (tid == 0) {
        int run = 0;
        int lo = (b < S1B) ? 0 : S1B;
        for (int j = lo; j < b; ++j) run += sb[j];
        s_boff = run;
        if (b == 0) {
            int t1 = 0, t2 = 0;
            for (int j = 0; j < S1B; ++j) t1 += sb[j];
            for (int j = S1B; j < SB; ++j) t2 += sb[j];
            g_off1[N1C] = t1;
            g_off2[N2C] = t2;
        }
    }

    int v[4], local = 0;
    int i0 = base + tid * 4;
#pragma unroll
    for (int k = 0; k < 4; ++k) {
        int idx = i0 + k;
        v[k] = (idx < n) ? cnt[idx] : 0;
        local += v[k];
    }
#pragma unroll
    for (int k = 0; k < 4; ++k) {      // restore cnt==0 for next replay
        int idx = i0 + k;
        if (idx < n) cnt[idx] = 0;
    }
    int incl = local;
#pragma unroll
    for (int o = 1; o < 32; o <<= 1) {
        int y = __shfl_up_sync(~0u, incl, o);
        if (lane >= o) incl += y;
    }
    if (lane == 31) wsum[wid] = incl;
    __syncthreads();
    if (wid == 0 && lane < 8) {
        int w = wsum[lane], wi = w;
#pragma unroll
        for (int o = 1; o < 8; o <<= 1) {
            int y = __shfl_up_sync(0xff, wi, o);
            if (lane >= o) wi += y;
        }
        wsum[lane] = wi - w;
    }
    __syncthreads();
    int run = incl - local + wsum[wid] + s_boff;
#pragma unroll
    for (int k = 0; k < 4; ++k) {
        int idx = i0 + k;
        if (idx < n) { off[idx] = run; cur[idx] = run; }
        run += v[k];
    }
}

// ---- counting-sort fill, 8 edges/thread (overlapped ATOMG chains) ----
__global__ void k_fill(const int* __restrict__ src1, const int* __restrict__ dst1,
                       const int* __restrict__ src2, const int* __restrict__ dst2,
                       int E1, int E2) {
    int t  = blockIdx.x * blockDim.x + threadIdx.x;
    int T1 = (E1 + 7) >> 3;
    const int* src; const int* dst; int* cur; int* srt; int E, base;
    if (t < T1) { src = src1; dst = dst1; cur = g_cur1; srt = g_srt1; E = E1; base = t * 8; }
    else {
        src = src2; dst = dst2; cur = g_cur2; srt = g_srt2; E = E2;
        base = (t - T1) * 8;
        if (base >= E2) return;
    }
    int d[8], s[8]; bool ok[8];
#pragma unroll
    for (int k = 0; k < 8; ++k) {
        int i = base + k;
        ok[k] = i < E;
        int i2 = ok[k] ? i : base;
        d[k] = dst[i2]; s[k] = src[i2];
    }
    int p[8];
#pragma unroll
    for (int k = 0; k < 8; ++k)
        if (ok[k]) p[k] = atomicAdd(&cur[d[k]], 1);
#pragma unroll
    for (int k = 0; k < 8; ++k)
        if (ok[k]) srt[p[k]] = s[k];
}

// ---- warp-per-dst MEAN aggregation; L==1 rounds result to tf32 ----
template <int L>
__global__ void k_agg(const float* __restrict__ xext) {
    const float* xs  = (L == 1) ? xext   : g_h;
    const int*   off = (L == 1) ? g_off1 : g_off2;
    const int*   srt = (L == 1) ? g_srt1 : g_srt2;
    float*       agg = (L == 1) ? g_agg1 : g_agg2;
    const int    nd  = (L == 1) ? N1C    : N2C;

    int w    = (blockIdx.x * blockDim.x + threadIdx.x) >> 5;
    int lane = threadIdx.x & 31;
    if (w >= nd) return;

    int b = __ldg(off + w), e = __ldg(off + w + 1);
    float4 acc = make_float4(0.f, 0.f, 0.f, 0.f);
    int j = b;
    for (; j + 8 <= e; j += 8) {
        int sI[8];
#pragma unroll
        for (int k = 0; k < 8; ++k) sI[k] = __ldg(srt + j + k);
        float4 v[8];
#pragma unroll
        for (int k = 0; k < 8; ++k)
            v[k] = *(const float4*)(xs + (size_t)sI[k] * DD + lane * 4);
#pragma unroll
        for (int k = 0; k < 8; ++k) {
            acc.x += v[k].x; acc.y += v[k].y; acc.z += v[k].z; acc.w += v[k].w;
        }
    }
    if (j + 4 <= e) {
        int sI[4];
#pragma unroll
        for (int k = 0; k < 4; ++k) sI[k] = __ldg(srt + j + k);
        float4 v[4];
#pragma unroll
        for (int k = 0; k < 4; ++k)
            v[k] = *(const float4*)(xs + (size_t)sI[k] * DD + lane * 4);
#pragma unroll
        for (int k = 0; k < 4; ++k) {
            acc.x += v[k].x; acc.y += v[k].y; acc.z += v[k].z; acc.w += v[k].w;
        }
        j += 4;
    }
    for (; j < e; ++j) {
        int s = __ldg(srt + j);
        float4 v = *(const float4*)(xs + (size_t)s * DD + lane * 4);
        acc.x += v.x; acc.y += v.y; acc.z += v.z; acc.w += v.w;
    }
    float inv = 1.0f / fmaxf((float)(e - b), 1.0f);
    acc.x *= inv; acc.y *= inv; acc.z *= inv; acc.w *= inv;
    if (L == 1) {   // pre-round so the mma's tf32 truncation is lossless
        acc.x = f2tf_rna(acc.x); acc.y = f2tf_rna(acc.y);
        acc.z = f2tf_rna(acc.z); acc.w = f2tf_rna(acc.w);
    }
    *(float4*)(agg + (size_t)w * DD + lane * 4) = acc;
}

// -------- tf32 layer-1 GEMM, cp.async 3-stage pipeline (1 sync/tile) --------
__device__ __forceinline__ void cp16(float* smem_dst, const float* gsrc, int ssz) {
    unsigned d = (unsigned)__cvta_generic_to_shared(smem_dst);
    asm volatile("cp.async.ca.shared.global [%0], [%1], 16, %2;"
                 :: "r"(d), "l"(gsrc), "r"(ssz));
}

#define SAGE1_STR   36
#define SAGE1_STAGE (2 * 128 * SAGE1_STR)           // floats per stage (A+B)
#define SAGE1_SMEM  (3 * SAGE1_STAGE * 4)           // 3 stages = 110592 bytes

__global__ void __launch_bounds__(256)
k_sage1_mma(const float* __restrict__ xd,
            const float* __restrict__ bias) {
    constexpr int BM = 128, STR = SAGE1_STR;
    extern __shared__ float smemf[];

    int tid  = threadIdx.x;
    int row0 = blockIdx.x * BM;

    int warp = tid >> 5, lane = tid & 31;
    int wm = warp & 3, wn = warp >> 2;
    int lr = lane >> 2, lc = lane & 3;

    float acc[2][8][4];
#pragma unroll
    for (int i = 0; i < 2; ++i)
#pragma unroll
        for (int j = 0; j < 8; ++j)
#pragma unroll
            for (int q = 0; q < 4; ++q) acc[i][j][q] = 0.f;

    auto load_tile = [&](int kt, int s) {
        const bool  first = (kt < 4);
        const int   k0    = (kt & 3) * 32;
        const float* Asrc = first ? g_agg1 : xd;
        const float* Bsrc = first ? g_W1l : g_W1r;
        float* Ab = smemf + s * SAGE1_STAGE;
        float* Bb = Ab + 128 * STR;
#pragma unroll
        for (int t = 0; t < 4; ++t) {
            int idx = tid + t * 256;               // [0,1024)
            int r = idx >> 3, kc = (idx & 7) * 4;  // r in [0,128)
            int row = row0 + r;
            bool okA = row < N1C;
            cp16(Ab + r * STR + kc,
                 Asrc + (size_t)(okA ? row : 0) * 128 + k0 + kc, okA ? 16 : 0);
            cp16(Bb + r * STR + kc, Bsrc + r * 128 + k0 + kc, 16);
        }
        asm volatile("cp.async.commit_group;");
    };

    load_tile(0, 0);
    load_tile(1, 1);

#pragma unroll 1
    for (int kt = 0; kt < 8; ++kt) {
        // tile kt ready when ≤1 group outstanding (groups complete in order)
        if (kt < 7) asm volatile("cp.async.wait_group 1;");
        else        asm volatile("cp.async.wait_group 0;");
        __syncthreads();   // also guards stage (kt+2)%3 overwrite below

        if (kt + 2 < 8) load_tile(kt + 2, (kt + 2) % 3);

        const unsigned* As = (const unsigned*)(smemf + (kt % 3) * SAGE1_STAGE);
        const unsigned* Bs = As + 128 * STR;

#pragma unroll
        for (int ks = 0; ks < 4; ++ks) {
            int kb = ks * 8;
            unsigned a[2][4], b[8][2];
#pragma unroll
            for (int i = 0; i < 2; ++i) {
                int r = wm * 32 + i * 16 + lr;
                a[i][0] = As[r * STR + kb + lc];
                a[i][1] = As[(r + 8) * STR + kb + lc];
                a[i][2] = As[r * STR + kb + lc + 4];
                a[i][3] = As[(r + 8) * STR + kb + lc + 4];
            }
#pragma unroll
            for (int j = 0; j < 8; ++j) {
                int n = wn * 64 + j * 8 + lr;
                b[j][0] = Bs[n * STR + kb + lc];
                b[j][1] = Bs[n * STR + kb + lc + 4];
            }
#pragma unroll
            for (int i = 0; i < 2; ++i)
#pragma unroll
                for (int j = 0; j < 8; ++j)
                    asm volatile(
                        "mma.sync.aligned.m16n8k8.row.col.f32.tf32.tf32.f32 "
                        "{%0,%1,%2,%3}, {%4,%5,%6,%7}, {%8,%9}, {%0,%1,%2,%3};"
                        : "+f"(acc[i][j][0]), "+f"(acc[i][j][1]),
                          "+f"(acc[i][j][2]), "+f"(acc[i][j][3])
                        : "r"(a[i][0]), "r"(a[i][1]), "r"(a[i][2]), "r"(a[i][3]),
                          "r"(b[j][0]), "r"(b[j][1]));
        }
        // no trailing sync: 3-stage ring means the next overwrite of this
        // stage is 2 iterations away, guarded by that iteration's sync.
    }

#pragma unroll
    for (int i = 0; i < 2; ++i) {
#pragma unroll
        for (int j = 0; j < 8; ++j) {
            int col = wn * 64 + j * 8 + 2 * lc;
            float b0 = bias[col], b1 = bias[col + 1];
            int r0 = row0 + wm * 32 + i * 16 + lr;
            if (r0 < N1C) {
                g_h[(size_t)r0 * 128 + col]     = fmaxf(acc[i][j][0] + b0, 0.f);
                g_h[(size_t)r0 * 128 + col + 1] = fmaxf(acc[i][j][1] + b1, 0.f);
            }
            int r1 = r0 + 8;
            if (r1 < N1C) {
                g_h[(size_t)r1 * 128 + col]     = fmaxf(acc[i][j][2] + b0, 0.f);
                g_h[(size_t)r1 * 128 + col + 1] = fmaxf(acc[i][j][3] + b1, 0.f);
            }
        }
    }
}

// ---------------- SIMT fp32 layer-2 GEMM (small) ----------------
__global__ void k_sage2(const float* __restrict__ Wl,
                        const float* __restrict__ Wr,
                        const float* __restrict__ bias,
                        float* __restrict__ out, int M) {
    constexpr int BM = 64, KT = 32, BN = 64, TN = 4;
    __shared__ float As[BM * (KT + 1)];
    __shared__ float Bs[KT * (BN + 1)];

    int tid  = threadIdx.x;
    int row0 = blockIdx.x * BM;

    int tcol = tid & 15;
    int trow = tid >> 4;

    float acc[4][TN];
#pragma unroll
    for (int i = 0; i < 4; ++i)
#pragma unroll
        for (int j = 0; j < TN; ++j) acc[i][j] = 0.f;

#pragma unroll 1
    for (int kt = 0; kt < 8; ++kt) {
        const bool  first = (kt < 4);
        const int   k0    = (kt & 3) * KT;
        const float* Asrc = first ? g_agg2 : g_h;
        const float* Bsrc = first ? Wl : Wr;

        __syncthreads();
#pragma unroll
        for (int t = 0; t < (BM * KT) / 256; ++t) {
            int idx = tid + t * 256;
            int r = idx >> 5, kk = idx & 31;
            int row = row0 + r;
            As[r * (KT + 1) + kk] = (row < M) ? Asrc[(size_t)row * 128 + k0 + kk] : 0.f;
        }
#pragma unroll
        for (int t = 0; t < (BN * KT) / 256; ++t) {
            int idx = tid + t * 256;
            int n = idx >> 5, kk = idx & 31;
            Bs[kk * (BN + 1) + n] = Bsrc[n * 128 + k0 + kk];
        }
        __syncthreads();

#pragma unroll
        for (int kk = 0; kk < KT; ++kk) {
            float a[4];
#pragma unroll
            for (int i = 0; i < 4; ++i)
                a[i] = As[(trow * 4 + i) * (KT + 1) + kk];
#pragma unroll
            for (int j = 0; j < TN; ++j) {
                float bv = Bs[kk * (BN + 1) + tcol + j * 16];
#pragma unroll
                for (int i = 0; i < 4; ++i)
                    acc[i][j] = fmaf(a[i], bv, acc[i][j]);
            }
        }
    }

#pragma unroll
    for (int i = 0; i < 4; ++i) {
        int row = row0 + trow * 4 + i;
        if (row >= M) continue;
#pragma unroll
        for (int j = 0; j < TN; ++j) {
            int col = tcol + j * 16;
            float v = acc[i][j] + bias[col];
            out[(size_t)row * BN + col] = fmaxf(v, 0.f);
        }
    }
}

extern "C" void kernel_launch(void* const* d_in, const int* in_sizes, int n_in,
                              void* d_out, int out_size) {
    const float* x    = (const float*)d_in[0];
    const float* W1_l = (const float*)d_in[1];
    const float* b1_l = (const float*)d_in[2];
    const float* W1_r = (const float*)d_in[3];
    const float* W2_l = (const float*)d_in[4];
    const float* b2_l = (const float*)d_in[5];
    const float* W2_r = (const float*)d_in[6];
    const int*   src1 = (const int*)d_in[7];
    const int*   dst1 = (const int*)d_in[8];
    const int*   src2 = (const int*)d_in[9];
    const int*   dst2 = (const int*)d_in[10];
    float* out = (float*)d_out;

    int E1 = in_sizes[7];
    int E2 = in_sizes[9];

    int T  = ((E1 + 7) >> 3) + ((E2 + 7) >> 3);

    // host-side attribute set (capture-time only; idempotent)
    cudaFuncSetAttribute(k_sage1_mma,
                         cudaFuncAttributeMaxDynamicSharedMemorySize, SAGE1_SMEM);

    k_hist<<<(T + 255) / 256, 256>>>(dst1, dst2, E1, E2, W1_l, W1_r);
    k_s1<<<SB, 256>>>();
    k_s3<<<SB, 256>>>();
    k_fill<<<(T + 255) / 256, 256>>>(src1, dst1, src2, dst2, E1, E2);

    k_agg<1><<<(N1C * 32 + 255) / 256, 256>>>(x);
    k_sage1_mma<<<(N1C + 127) / 128, 256, SAGE1_SMEM>>>(x, b1_l);

    k_agg<2><<<(N2C * 32 + 255) / 256, 256>>>(nullptr);
    k_sage2<<<(N2C + 63) / 64, 256>>>(W2_l, W2_r, b2_l, out, N2C);
}

// round 16
// speedup vs baseline: 1.0482x; 1.0482x over previous
#include <cuda_runtime.h>

#define DD  128
#define N1C 50000
#define N2C 5000
#define E1C 1000000
#define E2C 50000

#define S1B 49          // ceil(N1C/1024)
#define S2B 5           // ceil(N2C/1024)
#define SB  (S1B + S2B)

// Scratch (device globals — no allocation allowed; zero-initialized at load)
__device__ float g_agg1[N1C * DD];   // tf32-rounded mean after k_agg<1>
__device__ float g_h[N1C * DD];
__device__ float g_agg2[N2C * DD];   // fp32 mean (layer-2 is fp32 SIMT)
__device__ float g_W1l[DD * DD], g_W1r[DD * DD];   // tf32-rounded weights
__device__ int g_cnt1[N1C], g_off1[N1C + 1], g_cur1[N1C];
__device__ int g_cnt2[N2C], g_off2[N2C + 1], g_cur2[N2C];
__device__ int g_srt1[E1C], g_srt2[E2C];
__device__ int g_bsum[SB];

__device__ __forceinline__ float f2tf_rna(float f) {
    unsigned u;
    asm("cvt.rna.tf32.f32 %0, %1;" : "=r"(u) : "f"(f));
    return __uint_as_float(u);
}

// ---- degree histogram (8 edges/thread, int4 loads) + weight rounding;
//      cnt zero on entry — invariant re-established by k_s3 ----
__global__ void k_hist(const int* __restrict__ dst1,
                       const int* __restrict__ dst2, int E1, int E2,
                       const float* __restrict__ Wl,
                       const float* __restrict__ Wr) {
    int t  = blockIdx.x * blockDim.x + threadIdx.x;
    if (t < DD * DD) {
        g_W1l[t] = f2tf_rna(Wl[t]);
        g_W1r[t] = f2tf_rna(Wr[t]);
    }
    int T1 = (E1 + 7) >> 3;
    const int* dst; int* cnt; int E, base;
    if (t < T1) { dst = dst1; cnt = g_cnt1; E = E1; base = t * 8; }
    else {
        dst = dst2; cnt = g_cnt2; E = E2;
        base = (t - T1) * 8;
        if (base >= E2) return;
    }
    if (base + 8 <= E) {   // fast path: two vector loads
        int4 a = *(const int4*)(dst + base);
        int4 b = *(const int4*)(dst + base + 4);
        atomicAdd(&cnt[a.x], 1); atomicAdd(&cnt[a.y], 1);
        atomicAdd(&cnt[a.z], 1); atomicAdd(&cnt[a.w], 1);
        atomicAdd(&cnt[b.x], 1); atomicAdd(&cnt[b.y], 1);
        atomicAdd(&cnt[b.z], 1); atomicAdd(&cnt[b.w], 1);
    } else {
        for (int i = base; i < E; ++i) atomicAdd(&cnt[dst[i]], 1);
    }
}

// ---- scan phase 1: per-block (1024 elems) totals ----
__global__ void k_s1() {
    __shared__ int ws[8];
    int b = blockIdx.x, tid = threadIdx.x;
    const int* cnt; int n, base;
    if (b < S1B) { cnt = g_cnt1; n = N1C; base = b * 1024; }
    else         { cnt = g_cnt2; n = N2C; base = (b - S1B) * 1024; }

    int s = 0, i0 = base + tid * 4;
#pragma unroll
    for (int k = 0; k < 4; ++k) {
        int idx = i0 + k;
        if (idx < n) s += cnt[idx];
    }
    for (int o = 16; o; o >>= 1) s += __shfl_down_sync(~0u, s, o);
    if ((tid & 31) == 0) ws[tid >> 5] = s;
    __syncthreads();
    if (tid == 0) {
        int tot = 0;
#pragma unroll
        for (int w = 0; w < 8; ++w) tot += ws[w];
        g_bsum[b] = tot;
    }
}

// ---- scan phase 2+3 fused; zeroes cnt after use (restores invariant) ----
__global__ void k_s3() {
    __shared__ int wsum[8];
    __shared__ int sb[SB];
    __shared__ int s_boff;
    int b = blockIdx.x, tid = threadIdx.x;
    int lane = tid & 31, wid = tid >> 5;
    int* cnt; int* off; int* cur; int n, base;
    if (b < S1B) { cnt = g_cnt1; off = g_off1; cur = g_cur1; n = N1C; base = b * 1024; }
    else { cnt = g_cnt2; off = g_off2; cur = g_cur2; n = N2C; base = (b - S1B) * 1024; }

    if (tid < SB) sb[tid] = g_bsum[tid];
    __syncthreads();
    if (tid == 0) {
        int run = 0;
        int lo = (b < S1B) ? 0 : S1B;
        for (int j = lo; j < b; ++j) run += sb[j];
        s_boff = run;
        if (b == 0) {
            int t1 = 0, t2 = 0;
            for (int j = 0; j < S1B; ++j) t1 += sb[j];
            for (int j = S1B; j < SB; ++j) t2 += sb[j];
            g_off1[N1C] = t1;
            g_off2[N2C] = t2;
        }
    }

    int v[4], local = 0;
    int i0 = base + tid * 4;
#pragma unroll
    for (int k = 0; k < 4; ++k) {
        int idx = i0 + k;
        v[k] = (idx < n) ? cnt[idx] : 0;
        local += v[k];
    }
#pragma unroll
    for (int k = 0; k < 4; ++k) {      // restore cnt==0 for next replay
        int idx = i0 + k;
        if (idx < n) cnt[idx] = 0;
    }
    int incl = local;
#pragma unroll
    for (int o = 1; o < 32; o <<= 1) {
        int y = __shfl_up_sync(~0u, incl, o);
        if (lane >= o) incl += y;
    }
    if (lane == 31) wsum[wid] = incl;
    __syncthreads();
    if (wid == 0 && lane < 8) {
        int w = wsum[lane], wi = w;
#pragma unroll
        for (int o = 1; o < 8; o <<= 1) {
            int y = __shfl_up_sync(0xff, wi, o);
            if (lane >= o) wi += y;
        }
        wsum[lane] = wi - w;
    }
    __syncthreads();
    int run = incl - local + wsum[wid] + s_boff;
#pragma unroll
    for (int k = 0; k < 4; ++k) {
        int idx = i0 + k;
        if (idx < n) { off[idx] = run; cur[idx] = run; }
        run += v[k];
    }
}

// ---- counting-sort fill, 8 edges/thread, int4 loads ----
__global__ void k_fill(const int* __restrict__ src1, const int* __restrict__ dst1,
                       const int* __restrict__ src2, const int* __restrict__ dst2,
                       int E1, int E2) {
    int t  = blockIdx.x * blockDim.x + threadIdx.x;
    int T1 = (E1 + 7) >> 3;
    const int* src; const int* dst; int* cur; int* srt; int E, base;
    if (t < T1) { src = src1; dst = dst1; cur = g_cur1; srt = g_srt1; E = E1; base = t * 8; }
    else {
        src = src2; dst = dst2; cur = g_cur2; srt = g_srt2; E = E2;
        base = (t - T1) * 8;
        if (base >= E2) return;
    }
    if (base + 8 <= E) {   // fast path: vector loads, batched atomics
        int4 da = *(const int4*)(dst + base);
        int4 db = *(const int4*)(dst + base + 4);
        int4 sa = *(const int4*)(src + base);
        int4 sb = *(const int4*)(src + base + 4);
        int d[8] = {da.x, da.y, da.z, da.w, db.x, db.y, db.z, db.w};
        int s[8] = {sa.x, sa.y, sa.z, sa.w, sb.x, sb.y, sb.z, sb.w};
        int p[8];
#pragma unroll
        for (int k = 0; k < 8; ++k) p[k] = atomicAdd(&cur[d[k]], 1);
#pragma unroll
        for (int k = 0; k < 8; ++k) srt[p[k]] = s[k];
    } else {
        for (int i = base; i < E; ++i) {
            int p = atomicAdd(&cur[dst[i]], 1);
            srt[p] = src[i];
        }
    }
}

// ---- warp-per-dst MEAN aggregation; L==1 rounds result to tf32 ----
template <int L>
__global__ void k_agg(const float* __restrict__ xext) {
    const float* xs  = (L == 1) ? xext   : g_h;
    const int*   off = (L == 1) ? g_off1 : g_off2;
    const int*   srt = (L == 1) ? g_srt1 : g_srt2;
    float*       agg = (L == 1) ? g_agg1 : g_agg2;
    const int    nd  = (L == 1) ? N1C    : N2C;

    int w    = (blockIdx.x * blockDim.x + threadIdx.x) >> 5;
    int lane = threadIdx.x & 31;
    if (w >= nd) return;

    int b = __ldg(off + w), e = __ldg(off + w + 1);
    float4 acc = make_float4(0.f, 0.f, 0.f, 0.f);
    int j = b;
    for (; j + 8 <= e; j += 8) {
        int sI[8];
#pragma unroll
        for (int k = 0; k < 8; ++k) sI[k] = __ldg(srt + j + k);
        float4 v[8];
#pragma unroll
        for (int k = 0; k < 8; ++k)
            v[k] = *(const float4*)(xs + (size_t)sI[k] * DD + lane * 4);
#pragma unroll
        for (int k = 0; k < 8; ++k) {
            acc.x += v[k].x; acc.y += v[k].y; acc.z += v[k].z; acc.w += v[k].w;
        }
    }
    if (j + 4 <= e) {
        int sI[4];
#pragma unroll
        for (int k = 0; k < 4; ++k) sI[k] = __ldg(srt + j + k);
        float4 v[4];
#pragma unroll
        for (int k = 0; k < 4; ++k)
            v[k] = *(const float4*)(xs + (size_t)sI[k] * DD + lane * 4);
#pragma unroll
        for (int k = 0; k < 4; ++k) {
            acc.x += v[k].x; acc.y += v[k].y; acc.z += v[k].z; acc.w += v[k].w;
        }
        j += 4;
    }
    for (; j < e; ++j) {
        int s = __ldg(srt + j);
        float4 v = *(const float4*)(xs + (size_t)s * DD + lane * 4);
        acc.x += v.x; acc.y += v.y; acc.z += v.z; acc.w += v.w;
    }
    float inv = 1.0f / fmaxf((float)(e - b), 1.0f);
    acc.x *= inv; acc.y *= inv; acc.z *= inv; acc.w *= inv;
    if (L == 1) {   // pre-round so the mma's tf32 truncation is lossless
        acc.x = f2tf_rna(acc.x); acc.y = f2tf_rna(acc.y);
        acc.z = f2tf_rna(acc.z); acc.w = f2tf_rna(acc.w);
    }
    *(float4*)(agg + (size_t)w * DD + lane * 4) = acc;
}

// ---------------- tf32 layer-1 GEMM, cp.async 2-stage pipeline --------------
__device__ __forceinline__ void cp16(float* smem_dst, const float* gsrc, int ssz) {
    unsigned d = (unsigned)__cvta_generic_to_shared(smem_dst);
    asm volatile("cp.async.ca.shared.global [%0], [%1], 16, %2;"
                 :: "r"(d), "l"(gsrc), "r"(ssz));
}

#define SAGE1_STR   36
#define SAGE1_STAGE (2 * 128 * SAGE1_STR)           // floats per stage (A+B)
#define SAGE1_SMEM  (2 * SAGE1_STAGE * 4)           // bytes, 2 stages = 73728

__global__ void __launch_bounds__(256)
k_sage1_mma(const float* __restrict__ xd,
            const float* __restrict__ bias) {
    constexpr int BM = 128, STR = SAGE1_STR;
    extern __shared__ float smemf[];

    int tid  = threadIdx.x;
    int row0 = blockIdx.x * BM;

    int warp = tid >> 5, lane = tid & 31;
    int wm = warp & 3, wn = warp >> 2;
    int lr = lane >> 2, lc = lane & 3;

    float acc[2][8][4];
#pragma unroll
    for (int i = 0; i < 2; ++i)
#pragma unroll
        for (int j = 0; j < 8; ++j)
#pragma unroll
            for (int q = 0; q < 4; ++q) acc[i][j][q] = 0.f;

    auto load_tile = [&](int kt, int s) {
        const bool  first = (kt < 4);
        const int   k0    = (kt & 3) * 32;
        const float* Asrc = first ? g_agg1 : xd;
        const float* Bsrc = first ? g_W1l : g_W1r;
        float* Ab = smemf + s * SAGE1_STAGE;
        float* Bb = Ab + 128 * STR;
#pragma unroll
        for (int t = 0; t < 4; ++t) {
            int idx = tid + t * 256;               // [0,1024)
            int r = idx >> 3, kc = (idx & 7) * 4;  // r in [0,128)
            int row = row0 + r;
            bool okA = row < N1C;
            cp16(Ab + r * STR + kc,
                 Asrc + (size_t)(okA ? row : 0) * 128 + k0 + kc, okA ? 16 : 0);
            cp16(Bb + r * STR + kc, Bsrc + r * 128 + k0 + kc, 16);
        }
        asm volatile("cp.async.commit_group;");
    };

    load_tile(0, 0);

#pragma unroll 1
    for (int kt = 0; kt < 8; ++kt) {
        if (kt < 7) {
            load_tile(kt + 1, (kt + 1) & 1);
            asm volatile("cp.async.wait_group 1;");
        } else {
            asm volatile("cp.async.wait_group 0;");
        }
        __syncthreads();

        const unsigned* As = (const unsigned*)(smemf + (kt & 1) * SAGE1_STAGE);
        const unsigned* Bs = As + 128 * STR;

#pragma unroll
        for (int ks = 0; ks < 4; ++ks) {
            int kb = ks * 8;
            unsigned a[2][4], b[8][2];
#pragma unroll
            for (int i = 0; i < 2; ++i) {
                int r = wm * 32 + i * 16 + lr;
                a[i][0] = As[r * STR + kb + lc];
                a[i][1] = As[(r + 8) * STR + kb + lc];
                a[i][2] = As[r * STR + kb + lc + 4];
                a[i][3] = As[(r + 8) * STR + kb + lc + 4];
            }
#pragma unroll
            for (int j = 0; j < 8; ++j) {
                int n = wn * 64 + j * 8 + lr;
                b[j][0] = Bs[n * STR + kb + lc];
                b[j][1] = Bs[n * STR + kb + lc + 4];
            }
#pragma unroll
            for (int i = 0; i < 2; ++i)
#pragma unroll
                for (int j = 0; j < 8; ++j)
                    asm volatile(
                        "mma.sync.aligned.m16n8k8.row.col.f32.tf32.tf32.f32 "
                        "{%0,%1,%2,%3}, {%4,%5,%6,%7}, {%8,%9}, {%0,%1,%2,%3};"
                        : "+f"(acc[i][j][0]), "+f"(acc[i][j][1]),
                          "+f"(acc[i][j][2]), "+f"(acc[i][j][3])
                        : "r"(a[i][0]), "r"(a[i][1]), "r"(a[i][2]), "r"(a[i][3]),
                          "r"(b[j][0]), "r"(b[j][1]));
        }
        __syncthreads();   // stage reuse barrier
    }

#pragma unroll
    for (int i = 0; i < 2; ++i) {
#pragma unroll
        for (int j = 0; j < 8; ++j) {
            int col = wn * 64 + j * 8 + 2 * lc;
            float b0 = bias[col], b1 = bias[col + 1];
            int r0 = row0 + wm * 32 + i * 16 + lr;
            if (r0 < N1C) {
                g_h[(size_t)r0 * 128 + col]     = fmaxf(acc[i][j][0] + b0, 0.f);
                g_h[(size_t)r0 * 128 + col + 1] = fmaxf(acc[i][j][1] + b1, 0.f);
            }
            int r1 = r0 + 8;
            if (r1 < N1C) {
                g_h[(size_t)r1 * 128 + col]     = fmaxf(acc[i][j][2] + b0, 0.f);
                g_h[(size_t)r1 * 128 + col + 1] = fmaxf(acc[i][j][3] + b1, 0.f);
            }
        }
    }
}

// ---------------- SIMT fp32 layer-2 GEMM (small) ----------------
__global__ void k_sage2(const float* __restrict__ Wl,
                        const float* __restrict__ Wr,
                        const float* __restrict__ bias,
                        float* __restrict__ out, int M) {
    constexpr int BM = 64, KT = 32, BN = 64, TN = 4;
    __shared__ float As[BM * (KT + 1)];
    __shared__ float Bs[KT * (BN + 1)];

    int tid  = threadIdx.x;
    int row0 = blockIdx.x * BM;

    int tcol = tid & 15;
    int trow = tid >> 4;

    float acc[4][TN];
#pragma unroll
    for (int i = 0; i < 4; ++i)
#pragma unroll
        for (int j = 0; j < TN; ++j) acc[i][j] = 0.f;

#pragma unroll 1
    for (int kt = 0; kt < 8; ++kt) {
        const bool  first = (kt < 4);
        const int   k0    = (kt & 3) * KT;
        const float* Asrc = first ? g_agg2 : g_h;
        const float* Bsrc = first ? Wl : Wr;

        __syncthreads();
#pragma unroll
        for (int t = 0; t < (BM * KT) / 256; ++t) {
            int idx = tid + t * 256;
            int r = idx >> 5, kk = idx & 31;
            int row = row0 + r;
            As[r * (KT + 1) + kk] = (row < M) ? Asrc[(size_t)row * 128 + k0 + kk] : 0.f;
        }
#pragma unroll
        for (int t = 0; t < (BN * KT) / 256; ++t) {
            int idx = tid + t * 256;
            int n = idx >> 5, kk = idx & 31;
            Bs[kk * (BN + 1) + n] = Bsrc[n * 128 + k0 + kk];
        }
        __syncthreads();

#pragma unroll
        for (int kk = 0; kk < KT; ++kk) {
            float a[4];
#pragma unroll
            for (int i = 0; i < 4; ++i)
                a[i] = As[(trow * 4 + i) * (KT + 1) + kk];
#pragma unroll
            for (int j = 0; j < TN; ++j) {
                float bv = Bs[kk * (BN + 1) + tcol + j * 16];
#pragma unroll
                for (int i = 0; i < 4; ++i)
                    acc[i][j] = fmaf(a[i], bv, acc[i][j]);
            }
        }
    }

#pragma unroll
    for (int i = 0; i < 4; ++i) {
        int row = row0 + trow * 4 + i;
        if (row >= M) continue;
#pragma unroll
        for (int j = 0; j < TN; ++j) {
            int col = tcol + j * 16;
            float v = acc[i][j] + bias[col];
            out[(size_t)row * BN + col] = fmaxf(v, 0.f);
        }
    }
}

extern "C" void kernel_launch(void* const* d_in, const int* in_sizes, int n_in,
                              void* d_out, int out_size) {
    const float* x    = (const float*)d_in[0];
    const float* W1_l = (const float*)d_in[1];
    const float* b1_l = (const float*)d_in[2];
    const float* W1_r = (const float*)d_in[3];
    const float* W2_l = (const float*)d_in[4];
    const float* b2_l = (const float*)d_in[5];
    const float* W2_r = (const float*)d_in[6];
    const int*   src1 = (const int*)d_in[7];
    const int*   dst1 = (const int*)d_in[8];
    const int*   src2 = (const int*)d_in[9];
    const int*   dst2 = (const int*)d_in[10];
    float* out = (float*)d_out;

    int E1 = in_sizes[7];
    int E2 = in_sizes[9];

    int T  = ((E1 + 7) >> 3) + ((E2 + 7) >> 3);

    // host-side attribute set (capture-time only; idempotent)
    cudaFuncSetAttribute(k_sage1_mma,
                         cudaFuncAttributeMaxDynamicSharedMemorySize, SAGE1_SMEM);

    k_hist<<<(T + 255) / 256, 256>>>(dst1, dst2, E1, E2, W1_l, W1_r);
    k_s1<<<SB, 256>>>();
    k_s3<<<SB, 256>>>();
    k_fill<<<(T + 255) / 256, 256>>>(src1, dst1, src2, dst2, E1, E2);

    k_agg<1><<<(N1C * 32 + 255) / 256, 256>>>(x);
    k_sage1_mma<<<(N1C + 127) / 128, 256, SAGE1_SMEM>>>(x, b1_l);

    k_agg<2><<<(N2C * 32 + 255) / 256, 256>>>(nullptr);
    k_sage2<<<(N2C + 63) / 64, 256>>>(W2_l, W2_r, b2_l, out, N2C);
}

// round 17
// speedup vs baseline: 1.0616x; 1.0128x over previous
#include <cuda_runtime.h>

#define DD  128
#define N1C 50000
#define N2C 5000
#define E1C 1000000
#define E2C 50000

#define S1B 49          // ceil(N1C/1024)
#define S2B 5           // ceil(N2C/1024)
#define SB  (S1B + S2B)

// Scratch (device globals — no allocation allowed; zero-initialized at load)
__device__ float g_agg1[N1C * DD];   // tf32-rounded mean after k_agg<1>
__device__ float g_h[N1C * DD];
__device__ float g_agg2[N2C * DD];   // fp32 mean (layer-2 is fp32 SIMT)
__device__ float g_W1l[DD * DD], g_W1r[DD * DD];   // tf32-rounded weights
__device__ int g_cnt1[N1C], g_off1[N1C + 1], g_cur1[N1C];
__device__ int g_cnt2[N2C], g_off2[N2C + 1], g_cur2[N2C];
__device__ int g_srt1[E1C], g_srt2[E2C];
__device__ int g_bsum[SB];

// epoch grid-barrier state for the 54-block scan kernel (replay-safe)
__device__ unsigned g_arr, g_ep;

__device__ __forceinline__ float f2tf_rna(float f) {
    unsigned u;
    asm("cvt.rna.tf32.f32 %0, %1;" : "=r"(u) : "f"(f));
    return __uint_as_float(u);
}

// ---- degree histogram (8 edges/thread) + tf32 weight rounding fold-in;
//      cnt zero on entry — invariant re-established by k_scan ----
__global__ void k_hist(const int* __restrict__ dst1,
                       const int* __restrict__ dst2, int E1, int E2,
                       const float* __restrict__ Wl,
                       const float* __restrict__ Wr) {
    int t  = blockIdx.x * blockDim.x + threadIdx.x;
    if (t < DD * DD) {
        g_W1l[t] = f2tf_rna(Wl[t]);
        g_W1r[t] = f2tf_rna(Wr[t]);
    }
    int T1 = (E1 + 7) >> 3;
    if (t < T1) {
        int base = t * 8;
#pragma unroll
        for (int k = 0; k < 8; ++k) {
            int i = base + k;
            if (i < E1) atomicAdd(&g_cnt1[dst1[i]], 1);
        }
    } else {
        int base = (t - T1) * 8;
        if (base < E2) {
#pragma unroll
            for (int k = 0; k < 8; ++k) {
                int i = base + k;
                if (i < E2) atomicAdd(&g_cnt2[dst2[i]], 1);
            }
        }
    }
}

// ---- fused scan: per-chunk sums | grid barrier | scan + off/cur + cnt-zero ----
__global__ void __launch_bounds__(256)
k_scan() {
    __shared__ int ws[8];
    __shared__ int sb[SB];
    __shared__ int s_boff;
    int b = blockIdx.x, tid = threadIdx.x;
    int lane = tid & 31, wid = tid >> 5;
    int* cnt; int* off; int* cur; int n, base;
    if (b < S1B) { cnt = g_cnt1; off = g_off1; cur = g_cur1; n = N1C; base = b * 1024; }
    else         { cnt = g_cnt2; off = g_off2; cur = g_cur2; n = N2C; base = (b - S1B) * 1024; }

    // phase 1: chunk values + total (values kept in regs for phase 2)
    int v[4], local = 0;
    int i0 = base + tid * 4;
#pragma unroll
    for (int k = 0; k < 4; ++k) {
        int idx = i0 + k;
        v[k] = (idx < n) ? cnt[idx] : 0;
        local += v[k];
    }
#pragma unroll
    for (int k = 0; k < 4; ++k) {      // restore cnt==0 for next replay
        int idx = i0 + k;
        if (idx < n) cnt[idx] = 0;
    }
    int s = local;
    for (int o = 16; o; o >>= 1) s += __shfl_down_sync(~0u, s, o);
    if (lane == 0) ws[wid] = s;
    __syncthreads();
    if (tid == 0) {
        int tot = 0;
#pragma unroll
        for (int w = 0; w < 8; ++w) tot += ws[w];
        g_bsum[b] = tot;
    }

    // epoch grid barrier across the 54 co-resident blocks (replay-safe)
    __syncthreads();
    if (tid == 0) {
        __threadfence();
        unsigned snap = *(volatile unsigned*)&g_ep;
        unsigned t = atomicAdd(&g_arr, 1u);
        if (t == SB - 1) {
            g_arr = 0;
            __threadfence();
            atomicAdd(&g_ep, 1u);
        } else {
            while (*(volatile unsigned*)&g_ep == snap) { }
        }
        __threadfence();
    }
    __syncthreads();

    // phase 2: cross-chunk exclusive prefix + totals + local scan
    if (tid < SB) sb[tid] = g_bsum[tid];
    __syncthreads();
    if (tid == 0) {
        int run = 0;
        int lo = (b < S1B) ? 0 : S1B;
        for (int j = lo; j < b; ++j) run += sb[j];
        s_boff = run;
        if (b == 0) {
            int t1 = 0, t2 = 0;
            for (int j = 0; j < S1B; ++j) t1 += sb[j];
            for (int j = S1B; j < SB; ++j) t2 += sb[j];
            g_off1[N1C] = t1;
            g_off2[N2C] = t2;
        }
    }

    int incl = local;
#pragma unroll
    for (int o = 1; o < 32; o <<= 1) {
        int y = __shfl_up_sync(~0u, incl, o);
        if (lane >= o) incl += y;
    }
    if (lane == 31) ws[wid] = incl;
    __syncthreads();
    if (wid == 0 && lane < 8) {
        int w = ws[lane], wi = w;
#pragma unroll
        for (int o = 1; o < 8; o <<= 1) {
            int y = __shfl_up_sync(0xff, wi, o);
            if (lane >= o) wi += y;
        }
        ws[lane] = wi - w;
    }
    __syncthreads();
    int run = incl - local + ws[wid] + s_boff;
#pragma unroll
    for (int k = 0; k < 4; ++k) {
        int idx = i0 + k;
        if (idx < n) { off[idx] = run; cur[idx] = run; }
        run += v[k];
    }
}

// ---- counting-sort fill, 8 edges/thread (overlapped ATOMG chains) ----
__global__ void k_fill(const int* __restrict__ src1, const int* __restrict__ dst1,
                       const int* __restrict__ src2, const int* __restrict__ dst2,
                       int E1, int E2) {
    int t  = blockIdx.x * blockDim.x + threadIdx.x;
    int T1 = (E1 + 7) >> 3;
    const int* src; const int* dst; int* cur; int* srt; int E, base;
    if (t < T1) { src = src1; dst = dst1; cur = g_cur1; srt = g_srt1; E = E1; base = t * 8; }
    else {
        src = src2; dst = dst2; cur = g_cur2; srt = g_srt2; E = E2;
        base = (t - T1) * 8;
        if (base >= E2) return;
    }
    int d[8], s[8]; bool ok[8];
#pragma unroll
    for (int k = 0; k < 8; ++k) {
        int i = base + k;
        ok[k] = i < E;
        int i2 = ok[k] ? i : base;
        d[k] = dst[i2]; s[k] = src[i2];
    }
    int p[8];
#pragma unroll
    for (int k = 0; k < 8; ++k)
        if (ok[k]) p[k] = atomicAdd(&cur[d[k]], 1);
#pragma unroll
    for (int k = 0; k < 8; ++k)
        if (ok[k]) srt[p[k]] = s[k];
}

// ---- warp-per-dst MEAN aggregation; L==1 rounds result to tf32 ----
template <int L>
__global__ void k_agg(const float* __restrict__ xext) {
    const float* xs  = (L == 1) ? xext   : g_h;
    const int*   off = (L == 1) ? g_off1 : g_off2;
    const int*   srt = (L == 1) ? g_srt1 : g_srt2;
    float*       agg = (L == 1) ? g_agg1 : g_agg2;
    const int    nd  = (L == 1) ? N1C    : N2C;

    int w    = (blockIdx.x * blockDim.x + threadIdx.x) >> 5;
    int lane = threadIdx.x & 31;
    if (w >= nd) return;

    int b = __ldg(off + w), e = __ldg(off + w + 1);
    float4 acc = make_float4(0.f, 0.f, 0.f, 0.f);
    int j = b;
    for (; j + 8 <= e; j += 8) {
        int sI[8];
#pragma unroll
        for (int k = 0; k < 8; ++k) sI[k] = __ldg(srt + j + k);
        float4 v[8];
#pragma unroll
        for (int k = 0; k < 8; ++k)
            v[k] = *(const float4*)(xs + (size_t)sI[k] * DD + lane * 4);
#pragma unroll
        for (int k = 0; k < 8; ++k) {
            acc.x += v[k].x; acc.y += v[k].y; acc.z += v[k].z; acc.w += v[k].w;
        }
    }
    if (j + 4 <= e) {
        int sI[4];
#pragma unroll
        for (int k = 0; k < 4; ++k) sI[k] = __ldg(srt + j + k);
        float4 v[4];
#pragma unroll
        for (int k = 0; k < 4; ++k)
            v[k] = *(const float4*)(xs + (size_t)sI[k] * DD + lane * 4);
#pragma unroll
        for (int k = 0; k < 4; ++k) {
            acc.x += v[k].x; acc.y += v[k].y; acc.z += v[k].z; acc.w += v[k].w;
        }
        j += 4;
    }
    for (; j < e; ++j) {
        int s = __ldg(srt + j);
        float4 v = *(const float4*)(xs + (size_t)s * DD + lane * 4);
        acc.x += v.x; acc.y += v.y; acc.z += v.z; acc.w += v.w;
    }
    float inv = 1.0f / fmaxf((float)(e - b), 1.0f);
    acc.x *= inv; acc.y *= inv; acc.z *= inv; acc.w *= inv;
    if (L == 1) {   // pre-round so the mma's tf32 truncation is lossless
        acc.x = f2tf_rna(acc.x); acc.y = f2tf_rna(acc.y);
        acc.z = f2tf_rna(acc.z); acc.w = f2tf_rna(acc.w);
    }
    *(float4*)(agg + (size_t)w * DD + lane * 4) = acc;
}

// ---------------- tf32 layer-1 GEMM, cp.async 2-stage pipeline --------------
__device__ __forceinline__ void cp16(float* smem_dst, const float* gsrc, int ssz) {
    unsigned d = (unsigned)__cvta_generic_to_shared(smem_dst);
    asm volatile("cp.async.ca.shared.global [%0], [%1], 16, %2;"
                 :: "r"(d), "l"(gsrc), "r"(ssz));
}

#define SAGE1_STR   36
#define SAGE1_STAGE (2 * 128 * SAGE1_STR)           // floats per stage (A+B)
#define SAGE1_SMEM  (2 * SAGE1_STAGE * 4)           // bytes, 2 stages = 73728

__global__ void __launch_bounds__(256)
k_sage1_mma(const float* __restrict__ xd,
            const float* __restrict__ bias) {
    constexpr int BM = 128, STR = SAGE1_STR;
    extern __shared__ float smemf[];

    int tid  = threadIdx.x;
    int row0 = blockIdx.x * BM;

    int warp = tid >> 5, lane = tid & 31;
    int wm = warp & 3, wn = warp >> 2;
    int lr = lane >> 2, lc = lane & 3;

    float acc[2][8][4];
#pragma unroll
    for (int i = 0; i < 2; ++i)
#pragma unroll
        for (int j = 0; j < 8; ++j)
#pragma unroll
            for (int q = 0; q < 4; ++q) acc[i][j][q] = 0.f;

    auto load_tile = [&](int kt, int s) {
        const bool  first = (kt < 4);
        const int   k0    = (kt & 3) * 32;
        const float* Asrc = first ? g_agg1 : xd;
        const float* Bsrc = first ? g_W1l : g_W1r;
        float* Ab = smemf + s * SAGE1_STAGE;
        float* Bb = Ab + 128 * STR;
#pragma unroll
        for (int t = 0; t < 4; ++t) {
            int idx = tid + t * 256;               // [0,1024)
            int r = idx >> 3, kc = (idx & 7) * 4;  // r in [0,128)
            int row = row0 + r;
            bool okA = row < N1C;
            cp16(Ab + r * STR + kc,
                 Asrc + (size_t)(okA ? row : 0) * 128 + k0 + kc, okA ? 16 : 0);
            cp16(Bb + r * STR + kc, Bsrc + r * 128 + k0 + kc, 16);
        }
        asm volatile("cp.async.commit_group;");
    };

    load_tile(0, 0);

#pragma unroll 1
    for (int kt = 0; kt < 8; ++kt) {
        if (kt < 7) {
            load_tile(kt + 1, (kt + 1) & 1);
            asm volatile("cp.async.wait_group 1;");
        } else {
            asm volatile("cp.async.wait_group 0;");
        }
        __syncthreads();

        const unsigned* As = (const unsigned*)(smemf + (kt & 1) * SAGE1_STAGE);
        const unsigned* Bs = As + 128 * STR;

#pragma unroll
        for (int ks = 0; ks < 4; ++ks) {
            int kb = ks * 8;
            unsigned a[2][4], b[8][2];
#pragma unroll
            for (int i = 0; i < 2; ++i) {
                int r = wm * 32 + i * 16 + lr;
                a[i][0] = As[r * STR + kb + lc];
                a[i][1] = As[(r + 8) * STR + kb + lc];
                a[i][2] = As[r * STR + kb + lc + 4];
                a[i][3] = As[(r + 8) * STR + kb + lc + 4];
            }
#pragma unroll
            for (int j = 0; j < 8; ++j) {
                int n = wn * 64 + j * 8 + lr;
                b[j][0] = Bs[n * STR + kb + lc];
                b[j][1] = Bs[n * STR + kb + lc + 4];
            }
#pragma unroll
            for (int i = 0; i < 2; ++i)
#pragma unroll
                for (int j = 0; j < 8; ++j)
                    asm volatile(
                        "mma.sync.aligned.m16n8k8.row.col.f32.tf32.tf32.f32 "
                        "{%0,%1,%2,%3}, {%4,%5,%6,%7}, {%8,%9}, {%0,%1,%2,%3};"
                        : "+f"(acc[i][j][0]), "+f"(acc[i][j][1]),
                          "+f"(acc[i][j][2]), "+f"(acc[i][j][3])
                        : "r"(a[i][0]), "r"(a[i][1]), "r"(a[i][2]), "r"(a[i][3]),
                          "r"(b[j][0]), "r"(b[j][1]));
        }
        __syncthreads();   // stage reuse barrier
    }

#pragma unroll
    for (int i = 0; i < 2; ++i) {
#pragma unroll
        for (int j = 0; j < 8; ++j) {
            int col = wn * 64 + j * 8 + 2 * lc;
            float b0 = bias[col], b1 = bias[col + 1];
            int r0 = row0 + wm * 32 + i * 16 + lr;
            if (r0 < N1C) {
                g_h[(size_t)r0 * 128 + col]     = fmaxf(acc[i][j][0] + b0, 0.f);
                g_h[(size_t)r0 * 128 + col + 1] = fmaxf(acc[i][j][1] + b1, 0.f);
            }
            int r1 = r0 + 8;
            if (r1 < N1C) {
                g_h[(size_t)r1 * 128 + col]     = fmaxf(acc[i][j][2] + b0, 0.f);
                g_h[(size_t)r1 * 128 + col + 1] = fmaxf(acc[i][j][3] + b1, 0.f);
            }
        }
    }
}

// ---------------- SIMT fp32 layer-2 GEMM (small) ----------------
__global__ void k_sage2(const float* __restrict__ Wl,
                        const float* __restrict__ Wr,
                        const float* __restrict__ bias,
                        float* __restrict__ out, int M) {
    constexpr int BM = 64, KT = 32, BN = 64, TN = 4;
    __shared__ float As[BM * (KT + 1)];
    __shared__ float Bs[KT * (BN + 1)];

    int tid  = threadIdx.x;
    int row0 = blockIdx.x * BM;

    int tcol = tid & 15;
    int trow = tid >> 4;

    float acc[4][TN];
#pragma unroll
    for (int i = 0; i < 4; ++i)
#pragma unroll
        for (int j = 0; j < TN; ++j) acc[i][j] = 0.f;

#pragma unroll 1
    for (int kt = 0; kt < 8; ++kt) {
        const bool  first = (kt < 4);
        const int   k0    = (kt & 3) * KT;
        const float* Asrc = first ? g_agg2 : g_h;
        const float* Bsrc = first ? Wl : Wr;

        __syncthreads();
#pragma unroll
        for (int t = 0; t < (BM * KT) / 256; ++t) {
            int idx = tid + t * 256;
            int r = idx >> 5, kk = idx & 31;
            int row = row0 + r;
            As[r * (KT + 1) + kk] = (row < M) ? Asrc[(size_t)row * 128 + k0 + kk] : 0.f;
        }
#pragma unroll
        for (int t = 0; t < (BN * KT) / 256; ++t) {
            int idx = tid + t * 256;
            int n = idx >> 5, kk = idx & 31;
            Bs[kk * (BN + 1) + n] = Bsrc[n * 128 + k0 + kk];
        }
        __syncthreads();

#pragma unroll
        for (int kk = 0; kk < KT; ++kk) {
            float a[4];
#pragma unroll
            for (int i = 0; i < 4; ++i)
                a[i] = As[(trow * 4 + i) * (KT + 1) + kk];
#pragma unroll
            for (int j = 0; j < TN; ++j) {
                float bv = Bs[kk * (BN + 1) + tcol + j * 16];
#pragma unroll
                for (int i = 0; i < 4; ++i)
                    acc[i][j] = fmaf(a[i], bv, acc[i][j]);
            }
        }
    }

#pragma unroll
    for (int i = 0; i < 4; ++i) {
        int row = row0 + trow * 4 + i;
        if (row >= M) continue;
#pragma unroll
        for (int j = 0; j < TN; ++j) {
            int col = tcol + j * 16;
            float v = acc[i][j] + bias[col];
            out[(size_t)row * BN + col] = fmaxf(v, 0.f);
        }
    }
}

extern "C" void kernel_launch(void* const* d_in, const int* in_sizes, int n_in,
                              void* d_out, int out_size) {
    const float* x    = (const float*)d_in[0];
    const float* W1_l = (const float*)d_in[1];
    const float* b1_l = (const float*)d_in[2];
    const float* W1_r = (const float*)d_in[3];
    const float* W2_l = (const float*)d_in[4];
    const float* b2_l = (const float*)d_in[5];
    const float* W2_r = (const float*)d_in[6];
    const int*   src1 = (const int*)d_in[7];
    const int*   dst1 = (const int*)d_in[8];
    const int*   src2 = (const int*)d_in[9];
    const int*   dst2 = (const int*)d_in[10];
    float* out = (float*)d_out;

    int E1 = in_sizes[7];
    int E2 = in_sizes[9];

    int T  = ((E1 + 7) >> 3) + ((E2 + 7) >> 3);

    // host-side attribute set (capture-time only; idempotent)
    cudaFuncSetAttribute(k_sage1_mma,
                         cudaFuncAttributeMaxDynamicSharedMemorySize, SAGE1_SMEM);

    k_hist<<<(T + 255) / 256, 256>>>(dst1, dst2, E1, E2, W1_l, W1_r);
    k_scan<<<SB, 256>>>();
    k_fill<<<(T + 255) / 256, 256>>>(src1, dst1, src2, dst2, E1, E2);

    k_agg<1><<<(N1C * 32 + 255) / 256, 256>>>(x);
    k_sage1_mma<<<(N1C + 127) / 128, 256, SAGE1_SMEM>>>(x, b1_l);

    k_agg<2><<<(N2C * 32 + 255) / 256, 256>>>(nullptr);
    k_sage2<<<(N2C + 63) / 64, 256>>>(W2_l, W2_r, b2_l, out, N2C);
}